// round 10
// baseline (speedup 1.0000x reference)
#include <cuda_runtime.h>

#define NN 50000
#define DD 128
#define EE 800000

// ---- scratch (__device__ globals: allocation-free) ----
// Zero-initialized at module load. Each call restores the zero-invariant:
//   g_cntrow  zeroed by k_scan after reading
//   g_degcol  zeroed by k_scatter_dis after reading
//   g_maxbits never reset: zero decodes below any ford() value and atomicMax
//             with identical data is idempotent across graph replays
__device__ int   g_degcol[NN];     // degree over col (for norm)
__device__ int   g_cntrow[NN];     // degree over row (for CSR)
__device__ int   g_off[NN + 1];    // CSR row offsets
__device__ int   g_cursor[NN];     // scatter cursors
__device__ int   g_scol[EE];       // edges sorted by row: col ids
__device__ float g_dis[NN];        // deg_col^-0.5 (0 if deg==0)
__device__ unsigned int g_maxbits; // ordered-float max of x
__device__ float2 g_ppM;           // (pp*log2e, pp*max(x)*log2e) -- EX2-prefolded

// ordered-float encoding for atomicMax on signed floats
__device__ __forceinline__ unsigned int ford(float f) {
    unsigned int b = __float_as_uint(f);
    return (b & 0x80000000u) ? ~b : (b | 0x80000000u);
}
__device__ __forceinline__ float funord(unsigned int u) {
    unsigned int b = (u & 0x80000000u) ? (u & 0x7FFFFFFFu) : ~u;
    return __uint_as_float(b);
}
__device__ __forceinline__ float ex2(float z) {
    float r;
    asm("ex2.approx.f32 %0, %1;" : "=f"(r) : "f"(z));
    return r;
}

// L1: degree histograms (edge-parallel) + global max of x (grid-stride).
// The max loop's work fills issue slots otherwise idle behind atomic latency.
__global__ void k_count_max(const int* __restrict__ ei,
                            const float* __restrict__ x) {
    int e = blockIdx.x * blockDim.x + threadIdx.x;
    if (e < EE) {
        atomicAdd(&g_cntrow[ei[e]], 1);
        atomicAdd(&g_degcol[ei[EE + e]], 1);
    }

    float m = -3.402823466e38f;
    const float4* x4 = (const float4*)x;
    const int n4 = (NN * DD) / 4;
    const int gsz = gridDim.x * blockDim.x;
    for (int i = e; i < n4; i += gsz) {
        float4 v = x4[i];
        m = fmaxf(m, fmaxf(fmaxf(v.x, v.y), fmaxf(v.z, v.w)));
    }
#pragma unroll
    for (int o = 16; o; o >>= 1) m = fmaxf(m, __shfl_xor_sync(~0u, m, o));
    __shared__ float sm[32];
    int lane = threadIdx.x & 31, w = threadIdx.x >> 5;
    if (lane == 0) sm[w] = m;
    __syncthreads();
    if (w == 0) {
        m = (lane < (int)(blockDim.x >> 5)) ? sm[lane] : -3.402823466e38f;
#pragma unroll
        for (int o = 16; o; o >>= 1) m = fmaxf(m, __shfl_xor_sync(~0u, m, o));
        if (lane == 0) atomicMax(&g_maxbits, ford(m));
    }
}

// L2: single-block exclusive scan of g_cntrow -> g_off, g_cursor.
// Zeroes g_cntrow behind itself (restores invariant for next replay).
__global__ void k_scan() {
    const int C = (NN + 1023) / 1024;  // 49 elems per thread
    __shared__ int part[1024];
    int tid = threadIdx.x;
    int base = tid * C;
    int s = 0;
    for (int k = 0; k < C; k++) {
        int i = base + k;
        s += (i < NN) ? g_cntrow[i] : 0;
    }
    part[tid] = s;
    __syncthreads();
    for (int off = 1; off < 1024; off <<= 1) {
        int t = (tid >= off) ? part[tid - off] : 0;
        __syncthreads();
        part[tid] += t;
        __syncthreads();
    }
    int run = part[tid] - s;  // exclusive prefix of this chunk
    for (int k = 0; k < C; k++) {
        int i = base + k;
        if (i < NN) {
            int cnt = g_cntrow[i];
            g_cntrow[i] = 0;           // restore zero-invariant
            g_off[i] = run;
            g_cursor[i] = run;
            run += cnt;
        }
    }
    if (tid == 1023) g_off[NN] = run;
}

// L3: scatter cols into row-sorted order (edge-parallel) + dis[] for first
// NN threads (zeroing g_degcol behind) + ppM on thread 0.
__global__ void k_scatter_dis(const int* __restrict__ ei,
                              const float* __restrict__ p) {
    int e = blockIdx.x * blockDim.x + threadIdx.x;
    if (e < EE) {
        int r = ei[e];
        int c = ei[EE + e];
        int pos = atomicAdd(&g_cursor[r], 1);
        g_scol[pos] = c;
    }
    if (e < NN) {
        int dg = g_degcol[e];
        g_degcol[e] = 0;               // restore zero-invariant
        g_dis[e] = (dg > 0) ? rsqrtf((float)dg) : 0.0f;
    }
    if (e == 0) {
        const float LOG2E = 1.44269504088896340736f;
        float pp = 2.0f / (1.0f + __expf(-p[0]));
        float M = pp * funord(g_maxbits);
        g_ppM = make_float2(pp * LOG2E, M * LOG2E);
    }
}

// L4: 64-thread block = 2 independent warps, each warp handles one node.
// Lane l owns features 4l..4l+3 (one LDG.128 per edge).
__global__ void __launch_bounds__(64) k_main(const float* __restrict__ x,
                                             const float* __restrict__ eps,
                                             float* __restrict__ out) {
    const int w    = threadIdx.x >> 5;             // warp in block: 0/1
    const int lane = threadIdx.x & 31;
    const int r    = blockIdx.x * 2 + w;
    if (r >= NN) return;
    const int start = g_off[r];
    const int end   = g_off[r + 1];
    const float2 ppM = g_ppM;
    const float pp2 = ppM.x, M2 = ppM.y;   // EX2-prefolded
    const float4* __restrict__ x4 = (const float4*)x;

    __shared__ int   s_c[64];
    __shared__ float s_w[64];
    int*   sc = s_c + w * 32;
    float* sw = s_w + w * 32;

    float4 num = make_float4(0.f, 0.f, 0.f, 0.f);
    float4 den = make_float4(0.f, 0.f, 0.f, 0.f);

#define EDGE(t, wk)                                                   \
    {                                                                 \
        float ax = ex2(fmaf(pp2, (t).x, -M2)) * (wk);                 \
        float ay = ex2(fmaf(pp2, (t).y, -M2)) * (wk);                 \
        float az = ex2(fmaf(pp2, (t).z, -M2)) * (wk);                 \
        float aw = ex2(fmaf(pp2, (t).w, -M2)) * (wk);                 \
        den.x += ax; num.x = fmaf(ax, (t).x, num.x);                  \
        den.y += ay; num.y = fmaf(ay, (t).y, num.y);                  \
        den.z += az; num.z = fmaf(az, (t).z, num.z);                  \
        den.w += aw; num.w = fmaf(aw, (t).w, num.w);                  \
    }

    for (int base = start; base < end; base += 32) {
        int j = base + lane;
        if (j < end) {
            int c = g_scol[j];
            sc[lane] = c;
            sw[lane] = g_dis[c];
        }
        __syncwarp();
        int m = end - base;
        if (m > 32) m = 32;
        int k = 0;
        for (; k + 4 <= m; k += 4) {
            int   c0 = sc[k],     c1 = sc[k + 1], c2 = sc[k + 2], c3 = sc[k + 3];
            float w0 = sw[k],     w1 = sw[k + 1], w2 = sw[k + 2], w3 = sw[k + 3];
            float4 t0 = __ldg(&x4[c0 * 32 + lane]);
            float4 t1 = __ldg(&x4[c1 * 32 + lane]);
            float4 t2 = __ldg(&x4[c2 * 32 + lane]);
            float4 t3 = __ldg(&x4[c3 * 32 + lane]);
            EDGE(t0, w0) EDGE(t1, w1) EDGE(t2, w2) EDGE(t3, w3)
        }
        for (; k < m; k++) {
            int   c = sc[k];
            float wk = sw[k];
            float4 t = __ldg(&x4[c * 32 + lane]);
            EDGE(t, wk)
        }
        __syncwarp();
    }
#undef EDGE

    float dr = g_dis[r];
    float e1 = 1.0f + eps[0];
    float4 xv = __ldg(&x4[r * 32 + lane]);
    float4 o;
    o.x = __fdividef(dr * num.x, fmaf(dr, den.x, 1e-6f)) + e1 * xv.x;
    o.y = __fdividef(dr * num.y, fmaf(dr, den.y, 1e-6f)) + e1 * xv.y;
    o.z = __fdividef(dr * num.z, fmaf(dr, den.z, 1e-6f)) + e1 * xv.z;
    o.w = __fdividef(dr * num.w, fmaf(dr, den.w, 1e-6f)) + e1 * xv.w;
    ((float4*)out)[r * 32 + lane] = o;
}

extern "C" void kernel_launch(void* const* d_in, const int* in_sizes, int n_in,
                              void* d_out, int out_size) {
    const float* x   = (const float*)d_in[0];
    const int*   ei  = (const int*)d_in[1];
    const float* eps = (const float*)d_in[2];
    const float* p   = (const float*)d_in[3];
    float* out = (float*)d_out;

    k_count_max  <<<(EE + 255) / 256, 256>>>(ei, x);
    k_scan       <<<1, 1024>>>();
    k_scatter_dis<<<(EE + 255) / 256, 256>>>(ei, p);
    k_main       <<<(NN + 1) / 2, 64>>>(x, eps, out);
}

// round 11
// speedup vs baseline: 2.1781x; 2.1781x over previous
#include <cuda_runtime.h>

#define NN 50000
#define DD 128
#define EE 800000
#define NCHUNK 196   // ceil(NN/256)

// ---- scratch (__device__ globals: allocation-free) ----
// Zero-initialized at module load; every call restores the zero-invariant:
//   g_cntrow zeroed by k_scan3 after use; g_degcol zeroed by k_scatter_dis;
//   g_maxbits never reset (zero decodes below any ford() value, atomicMax
//   with identical data is idempotent across graph replays).
__device__ int   g_degcol[NN];     // degree over col (for norm)
__device__ int   g_cntrow[NN];     // degree over row (for CSR)
__device__ int   g_off[NN + 1];    // CSR row offsets
__device__ int   g_cursor[NN];     // scatter cursors
__device__ int   g_scol[EE];       // edges sorted by row: col ids
__device__ float g_dis[NN];        // deg_col^-0.5 (0 if deg==0)
__device__ int   g_bsum[NCHUNK];   // per-chunk sums (scan phase 1)
__device__ int   g_boff[NCHUNK];   // per-chunk exclusive offsets (phase 2)
__device__ unsigned int g_maxbits; // ordered-float max of x
__device__ float2 g_ppM;           // (pp*log2e, pp*max(x)*log2e) EX2-prefolded

__device__ __forceinline__ unsigned int ford(float f) {
    unsigned int b = __float_as_uint(f);
    return (b & 0x80000000u) ? ~b : (b | 0x80000000u);
}
__device__ __forceinline__ float funord(unsigned int u) {
    unsigned int b = (u & 0x80000000u) ? (u & 0x7FFFFFFFu) : ~u;
    return __uint_as_float(b);
}
__device__ __forceinline__ float ex2(float z) {
    float r;
    asm("ex2.approx.f32 %0, %1;" : "=f"(r) : "f"(z));
    return r;
}

// L1: pure edge histogram
__global__ void k_count(const int* __restrict__ ei) {
    int e = blockIdx.x * blockDim.x + threadIdx.x;
    if (e < EE) {
        atomicAdd(&g_cntrow[ei[e]], 1);
        atomicAdd(&g_degcol[ei[EE + e]], 1);
    }
}

// L2 (scan phase 1, 196 blocks x 256): local exclusive scan of each 256-chunk
// of g_cntrow into g_off; chunk sum into g_bsum. Also grid-strides x-max.
__global__ void __launch_bounds__(256) k_scan1(const float* __restrict__ x) {
    __shared__ int sh[256];
    int tid = threadIdx.x;
    int i = blockIdx.x * 256 + tid;
    int v = (i < NN) ? g_cntrow[i] : 0;
    sh[tid] = v;
    __syncthreads();
#pragma unroll
    for (int off = 1; off < 256; off <<= 1) {
        int t = (tid >= off) ? sh[tid - off] : 0;
        __syncthreads();
        sh[tid] += t;
        __syncthreads();
    }
    if (i < NN) g_off[i] = sh[tid] - v;          // exclusive local prefix
    if (tid == 255) g_bsum[blockIdx.x] = sh[255]; // chunk total

    // x-max reduction (independent of counts), grid-stride over float4s
    float m = -3.402823466e38f;
    const float4* x4 = (const float4*)x;
    const int n4 = (NN * DD) / 4;
    const int gsz = gridDim.x * blockDim.x;
    for (int k = blockIdx.x * 256 + tid; k < n4; k += gsz) {
        float4 t = x4[k];
        m = fmaxf(m, fmaxf(fmaxf(t.x, t.y), fmaxf(t.z, t.w)));
    }
#pragma unroll
    for (int o = 16; o; o >>= 1) m = fmaxf(m, __shfl_xor_sync(~0u, m, o));
    __shared__ float sm[8];
    int lane = tid & 31, w = tid >> 5;
    if (lane == 0) sm[w] = m;
    __syncthreads();
    if (w == 0) {
        m = (lane < 8) ? sm[lane] : -3.402823466e38f;
#pragma unroll
        for (int o = 4; o; o >>= 1) m = fmaxf(m, __shfl_xor_sync(~0u, m, o));
        if (lane == 0) atomicMax(&g_maxbits, ford(m));
    }
}

// L3 (scan phase 2, 1 block x 256): scan the 196 chunk sums; total is EE.
// Also compute ppM (maxbits complete after k_scan1).
__global__ void __launch_bounds__(256) k_scan2(const float* __restrict__ p) {
    __shared__ int sh[256];
    int tid = threadIdx.x;
    int v = (tid < NCHUNK) ? g_bsum[tid] : 0;
    sh[tid] = v;
    __syncthreads();
#pragma unroll
    for (int off = 1; off < 256; off <<= 1) {
        int t = (tid >= off) ? sh[tid - off] : 0;
        __syncthreads();
        sh[tid] += t;
        __syncthreads();
    }
    if (tid < NCHUNK) g_boff[tid] = sh[tid] - v;  // exclusive
    if (tid == 0) {
        g_off[NN] = EE;
        const float LOG2E = 1.44269504088896340736f;
        float pp = 2.0f / (1.0f + __expf(-p[0]));
        float M = pp * funord(g_maxbits);
        g_ppM = make_float2(pp * LOG2E, M * LOG2E);
    }
}

// L4 (scan phase 3, 196 blocks x 256): add chunk offset, emit off/cursor,
// zero g_cntrow (parallel self-cleaning).
__global__ void __launch_bounds__(256) k_scan3() {
    int i = blockIdx.x * 256 + threadIdx.x;
    if (i < NN) {
        int off = g_off[i] + g_boff[blockIdx.x];
        g_off[i] = off;
        g_cursor[i] = off;
        g_cntrow[i] = 0;          // restore zero-invariant
    }
}

// L5: scatter cols into row-sorted order + dis[] (zeroing g_degcol behind)
__global__ void k_scatter_dis(const int* __restrict__ ei) {
    int e = blockIdx.x * blockDim.x + threadIdx.x;
    if (e < EE) {
        int r = ei[e];
        int c = ei[EE + e];
        int pos = atomicAdd(&g_cursor[r], 1);
        g_scol[pos] = c;
    }
    if (e < NN) {
        int dg = g_degcol[e];
        g_degcol[e] = 0;          // restore zero-invariant
        g_dis[e] = (dg > 0) ? rsqrtf((float)dg) : 0.0f;
    }
}

// L6: 64-thread block = 2 independent warps, each warp handles one node.
// Lane l owns features 4l..4l+3 (one LDG.128 per edge).
__global__ void __launch_bounds__(64) k_main(const float* __restrict__ x,
                                             const float* __restrict__ eps,
                                             float* __restrict__ out) {
    const int w    = threadIdx.x >> 5;
    const int lane = threadIdx.x & 31;
    const int r    = blockIdx.x * 2 + w;
    if (r >= NN) return;
    const int start = g_off[r];
    const int end   = g_off[r + 1];
    const float2 ppM = g_ppM;
    const float pp2 = ppM.x, M2 = ppM.y;
    const float4* __restrict__ x4 = (const float4*)x;

    __shared__ int   s_c[64];
    __shared__ float s_w[64];
    int*   sc = s_c + w * 32;
    float* sw = s_w + w * 32;

    float4 num = make_float4(0.f, 0.f, 0.f, 0.f);
    float4 den = make_float4(0.f, 0.f, 0.f, 0.f);

#define EDGE(t, wk)                                                   \
    {                                                                 \
        float ax = ex2(fmaf(pp2, (t).x, -M2)) * (wk);                 \
        float ay = ex2(fmaf(pp2, (t).y, -M2)) * (wk);                 \
        float az = ex2(fmaf(pp2, (t).z, -M2)) * (wk);                 \
        float aw = ex2(fmaf(pp2, (t).w, -M2)) * (wk);                 \
        den.x += ax; num.x = fmaf(ax, (t).x, num.x);                  \
        den.y += ay; num.y = fmaf(ay, (t).y, num.y);                  \
        den.z += az; num.z = fmaf(az, (t).z, num.z);                  \
        den.w += aw; num.w = fmaf(aw, (t).w, num.w);                  \
    }

    for (int base = start; base < end; base += 32) {
        int j = base + lane;
        if (j < end) {
            int c = g_scol[j];
            sc[lane] = c;
            sw[lane] = g_dis[c];
        }
        __syncwarp();
        int m = end - base;
        if (m > 32) m = 32;
        int k = 0;
        for (; k + 4 <= m; k += 4) {
            int   c0 = sc[k],     c1 = sc[k + 1], c2 = sc[k + 2], c3 = sc[k + 3];
            float w0 = sw[k],     w1 = sw[k + 1], w2 = sw[k + 2], w3 = sw[k + 3];
            float4 t0 = __ldg(&x4[c0 * 32 + lane]);
            float4 t1 = __ldg(&x4[c1 * 32 + lane]);
            float4 t2 = __ldg(&x4[c2 * 32 + lane]);
            float4 t3 = __ldg(&x4[c3 * 32 + lane]);
            EDGE(t0, w0) EDGE(t1, w1) EDGE(t2, w2) EDGE(t3, w3)
        }
        for (; k < m; k++) {
            int   c = sc[k];
            float wk = sw[k];
            float4 t = __ldg(&x4[c * 32 + lane]);
            EDGE(t, wk)
        }
        __syncwarp();
    }
#undef EDGE

    float dr = g_dis[r];
    float e1 = 1.0f + eps[0];
    float4 xv = __ldg(&x4[r * 32 + lane]);
    float4 o;
    o.x = __fdividef(dr * num.x, fmaf(dr, den.x, 1e-6f)) + e1 * xv.x;
    o.y = __fdividef(dr * num.y, fmaf(dr, den.y, 1e-6f)) + e1 * xv.y;
    o.z = __fdividef(dr * num.z, fmaf(dr, den.z, 1e-6f)) + e1 * xv.z;
    o.w = __fdividef(dr * num.w, fmaf(dr, den.w, 1e-6f)) + e1 * xv.w;
    ((float4*)out)[r * 32 + lane] = o;
}

extern "C" void kernel_launch(void* const* d_in, const int* in_sizes, int n_in,
                              void* d_out, int out_size) {
    const float* x   = (const float*)d_in[0];
    const int*   ei  = (const int*)d_in[1];
    const float* eps = (const float*)d_in[2];
    const float* p   = (const float*)d_in[3];
    float* out = (float*)d_out;

    k_count      <<<(EE + 255) / 256, 256>>>(ei);
    k_scan1      <<<NCHUNK, 256>>>(x);
    k_scan2      <<<1, 256>>>(p);
    k_scan3      <<<NCHUNK, 256>>>();
    k_scatter_dis<<<(EE + 255) / 256, 256>>>(ei);
    k_main       <<<(NN + 1) / 2, 64>>>(x, eps, out);
}

// round 12
// speedup vs baseline: 2.2958x; 1.0540x over previous
#include <cuda_runtime.h>

#define NN 50000
#define DD 128
#define EE 800000
#define NCHUNK 196   // ceil(NN/256)

// ---- scratch (__device__ globals: allocation-free) ----
// Zero-initialized at module load; every call restores the zero-invariant:
//   g_cntrow zeroed by k_scan3 after use; g_degcol zeroed by k_scatter_dis;
//   g_maxbits never reset (zero decodes below any ford() value, atomicMax
//   with identical data is idempotent across graph replays).
__device__ int   g_degcol[NN];     // degree over col (for norm)
__device__ int   g_cntrow[NN];     // degree over row (for CSR)
__device__ int   g_off[NN + 1];    // CSR row offsets
__device__ int   g_cursor[NN];     // scatter cursors
__device__ int   g_scol[EE];       // edges sorted by row: col ids
__device__ float g_dis[NN];        // deg_col^-0.5 (0 if deg==0)
__device__ float g_ldis[NN];       // log2(dis) - M2  (-inf if deg==0)
__device__ int   g_bsum[NCHUNK];   // per-chunk sums (scan phase 1)
__device__ int   g_boff[NCHUNK];   // per-chunk exclusive offsets (phase 2)
__device__ unsigned int g_maxbits; // ordered-float max of x
__device__ float2 g_ppM;           // (pp*log2e, pp*max(x)*log2e) EX2-prefolded

__device__ __forceinline__ unsigned int ford(float f) {
    unsigned int b = __float_as_uint(f);
    return (b & 0x80000000u) ? ~b : (b | 0x80000000u);
}
__device__ __forceinline__ float funord(unsigned int u) {
    unsigned int b = (u & 0x80000000u) ? (u & 0x7FFFFFFFu) : ~u;
    return __uint_as_float(b);
}
__device__ __forceinline__ float ex2(float z) {
    float r;
    asm("ex2.approx.f32 %0, %1;" : "=f"(r) : "f"(z));
    return r;
}
__device__ __forceinline__ float lg2(float z) {
    float r;
    asm("lg2.approx.f32 %0, %1;" : "=f"(r) : "f"(z));
    return r;
}

// L1: pure edge histogram (EE == 3125*256 exactly, no bounds check)
__global__ void __launch_bounds__(256) k_count(const int* __restrict__ ei) {
    int e = blockIdx.x * 256 + threadIdx.x;
    atomicAdd(&g_cntrow[__ldg(&ei[e])], 1);
    atomicAdd(&g_degcol[__ldg(&ei[EE + e])], 1);
}

// L2 (scan phase 1, 196 blocks x 256): local exclusive scan of each 256-chunk
// of g_cntrow into g_off; chunk sum into g_bsum. Also grid-strides x-max.
__global__ void __launch_bounds__(256) k_scan1(const float* __restrict__ x) {
    __shared__ int sh[256];
    int tid = threadIdx.x;
    int i = blockIdx.x * 256 + tid;
    int v = (i < NN) ? g_cntrow[i] : 0;
    sh[tid] = v;
    __syncthreads();
#pragma unroll
    for (int off = 1; off < 256; off <<= 1) {
        int t = (tid >= off) ? sh[tid - off] : 0;
        __syncthreads();
        sh[tid] += t;
        __syncthreads();
    }
    if (i < NN) g_off[i] = sh[tid] - v;           // exclusive local prefix
    if (tid == 255) g_bsum[blockIdx.x] = sh[255]; // chunk total

    // x-max reduction (independent of counts), grid-stride over float4s
    float m = -3.402823466e38f;
    const float4* x4 = (const float4*)x;
    const int n4 = (NN * DD) / 4;
    const int gsz = gridDim.x * blockDim.x;
    for (int k = blockIdx.x * 256 + tid; k < n4; k += gsz) {
        float4 t = x4[k];
        m = fmaxf(m, fmaxf(fmaxf(t.x, t.y), fmaxf(t.z, t.w)));
    }
#pragma unroll
    for (int o = 16; o; o >>= 1) m = fmaxf(m, __shfl_xor_sync(~0u, m, o));
    __shared__ float sm[8];
    int lane = tid & 31, w = tid >> 5;
    if (lane == 0) sm[w] = m;
    __syncthreads();
    if (w == 0) {
        m = (lane < 8) ? sm[lane] : -3.402823466e38f;
#pragma unroll
        for (int o = 4; o; o >>= 1) m = fmaxf(m, __shfl_xor_sync(~0u, m, o));
        if (lane == 0) atomicMax(&g_maxbits, ford(m));
    }
}

// L3 (scan phase 2, 1 block x 256): scan the 196 chunk sums; total is EE.
// Also compute ppM (maxbits complete after k_scan1).
__global__ void __launch_bounds__(256) k_scan2(const float* __restrict__ p) {
    __shared__ int sh[256];
    int tid = threadIdx.x;
    int v = (tid < NCHUNK) ? g_bsum[tid] : 0;
    sh[tid] = v;
    __syncthreads();
#pragma unroll
    for (int off = 1; off < 256; off <<= 1) {
        int t = (tid >= off) ? sh[tid - off] : 0;
        __syncthreads();
        sh[tid] += t;
        __syncthreads();
    }
    if (tid < NCHUNK) g_boff[tid] = sh[tid] - v;  // exclusive
    if (tid == 0) {
        g_off[NN] = EE;
        const float LOG2E = 1.44269504088896340736f;
        float pp = 2.0f / (1.0f + __expf(-p[0]));
        float M = pp * funord(g_maxbits);
        g_ppM = make_float2(pp * LOG2E, M * LOG2E);
    }
}

// L4 (scan phase 3, 196 blocks x 256): add chunk offset, emit off/cursor,
// zero g_cntrow (parallel self-cleaning).
__global__ void __launch_bounds__(256) k_scan3() {
    int i = blockIdx.x * 256 + threadIdx.x;
    if (i < NN) {
        int off = g_off[i] + g_boff[blockIdx.x];
        g_off[i] = off;
        g_cursor[i] = off;
        g_cntrow[i] = 0;          // restore zero-invariant
    }
}

// L5: scatter cols into row-sorted order + dis[]/ldis[] (zeroing g_degcol).
// ldis = log2(dis) - M2 so k_main's exp folds the edge weight for free.
__global__ void __launch_bounds__(256) k_scatter_dis(const int* __restrict__ ei) {
    int e = blockIdx.x * 256 + threadIdx.x;
    int r = __ldg(&ei[e]);
    int c = __ldg(&ei[EE + e]);
    int pos = atomicAdd(&g_cursor[r], 1);
    g_scol[pos] = c;
    if (e < NN) {
        int dg = g_degcol[e];
        g_degcol[e] = 0;          // restore zero-invariant
        float M2 = g_ppM.y;
        if (dg > 0) {
            float dis = rsqrtf((float)dg);
            g_dis[e]  = dis;
            g_ldis[e] = lg2(dis) - M2;
        } else {
            g_dis[e]  = 0.0f;
            g_ldis[e] = -__int_as_float(0x7f800000); // -inf -> ex2() == 0
        }
    }
}

// L6: 64-thread block = 2 independent warps, each warp handles one node.
// Lane l owns features 4l..4l+3 (one LDG.128 per edge).
// Per feature: a = ex2(fma(pp2,t,lw)); den += a; num = fma(a,t,num).
__global__ void __launch_bounds__(64) k_main(const float* __restrict__ x,
                                             const float* __restrict__ eps,
                                             float* __restrict__ out) {
    const int w    = threadIdx.x >> 5;
    const int lane = threadIdx.x & 31;
    const int r    = blockIdx.x * 2 + w;
    if (r >= NN) return;
    const int start = g_off[r];
    const int end   = g_off[r + 1];
    const float pp2 = g_ppM.x;
    const float4* __restrict__ x4 = (const float4*)x;

    __shared__ int   s_c[64];
    __shared__ float s_w[64];
    int*   sc = s_c + w * 32;
    float* sw = s_w + w * 32;

    float4 num = make_float4(0.f, 0.f, 0.f, 0.f);
    float4 den = make_float4(0.f, 0.f, 0.f, 0.f);

#define EDGE(t, lw)                                                   \
    {                                                                 \
        float ax = ex2(fmaf(pp2, (t).x, (lw)));                       \
        float ay = ex2(fmaf(pp2, (t).y, (lw)));                       \
        float az = ex2(fmaf(pp2, (t).z, (lw)));                       \
        float aw = ex2(fmaf(pp2, (t).w, (lw)));                       \
        den.x += ax; num.x = fmaf(ax, (t).x, num.x);                  \
        den.y += ay; num.y = fmaf(ay, (t).y, num.y);                  \
        den.z += az; num.z = fmaf(az, (t).z, num.z);                  \
        den.w += aw; num.w = fmaf(aw, (t).w, num.w);                  \
    }

    for (int base = start; base < end; base += 32) {
        int j = base + lane;
        if (j < end) {
            int c = g_scol[j];
            sc[lane] = c;
            sw[lane] = g_ldis[c];
        }
        __syncwarp();
        int m = end - base;
        if (m > 32) m = 32;
        int k = 0;
        for (; k + 4 <= m; k += 4) {
            int   c0 = sc[k],     c1 = sc[k + 1], c2 = sc[k + 2], c3 = sc[k + 3];
            float w0 = sw[k],     w1 = sw[k + 1], w2 = sw[k + 2], w3 = sw[k + 3];
            float4 t0 = __ldg(&x4[c0 * 32 + lane]);
            float4 t1 = __ldg(&x4[c1 * 32 + lane]);
            float4 t2 = __ldg(&x4[c2 * 32 + lane]);
            float4 t3 = __ldg(&x4[c3 * 32 + lane]);
            EDGE(t0, w0) EDGE(t1, w1) EDGE(t2, w2) EDGE(t3, w3)
        }
        for (; k < m; k++) {
            int   c = sc[k];
            float lw = sw[k];
            float4 t = __ldg(&x4[c * 32 + lane]);
            EDGE(t, lw)
        }
        __syncwarp();
    }
#undef EDGE

    float dr = g_dis[r];
    float e1 = 1.0f + eps[0];
    float4 xv = __ldg(&x4[r * 32 + lane]);
    float4 o;
    o.x = __fdividef(dr * num.x, fmaf(dr, den.x, 1e-6f)) + e1 * xv.x;
    o.y = __fdividef(dr * num.y, fmaf(dr, den.y, 1e-6f)) + e1 * xv.y;
    o.z = __fdividef(dr * num.z, fmaf(dr, den.z, 1e-6f)) + e1 * xv.z;
    o.w = __fdividef(dr * num.w, fmaf(dr, den.w, 1e-6f)) + e1 * xv.w;
    ((float4*)out)[r * 32 + lane] = o;
}

extern "C" void kernel_launch(void* const* d_in, const int* in_sizes, int n_in,
                              void* d_out, int out_size) {
    const float* x   = (const float*)d_in[0];
    const int*   ei  = (const int*)d_in[1];
    const float* eps = (const float*)d_in[2];
    const float* p   = (const float*)d_in[3];
    float* out = (float*)d_out;

    k_count      <<<EE / 256, 256>>>(ei);
    k_scan1      <<<NCHUNK, 256>>>(x);
    k_scan2      <<<1, 256>>>(p);
    k_scan3      <<<NCHUNK, 256>>>();
    k_scatter_dis<<<EE / 256, 256>>>(ei);
    k_main       <<<(NN + 1) / 2, 64>>>(x, eps, out);
}

// round 13
// speedup vs baseline: 2.3453x; 1.0216x over previous
#include <cuda_runtime.h>

#define NN 50000
#define DD 128
#define EE 800000
#define NCHUNK 196   // ceil(NN/256)

// ---- scratch (__device__ globals: allocation-free) ----
// Zero-initialized at module load; every call restores/overwrites state:
//   g_cntrow zeroed by k_scan1 after reading; g_degcol zeroed by k_scatter_dis;
//   g_off/g_boff fully rewritten each call; g_maxbits never reset (zero decodes
//   below any ford() value; atomicMax with identical data is replay-idempotent).
__device__ int   g_degcol[NN];     // degree over col (for norm)
__device__ int   g_cntrow[NN];     // degree over row (for CSR)
__device__ int   g_off[NN];        // local prefix (excl -> incl after scatter)
__device__ int   g_scol[EE];       // edges sorted by row: col ids
__device__ float g_dis[NN];        // deg_col^-0.5 (0 if deg==0)
__device__ float g_ldis[NN];       // log2(dis) - M2  (-inf if deg==0)
__device__ int   g_bsum[NCHUNK];   // per-chunk sums (scan phase 1)
__device__ int   g_boff[NCHUNK];   // per-chunk exclusive offsets (phase 2)
__device__ unsigned int g_maxbits; // ordered-float max of x
__device__ float2 g_ppM;           // (pp*log2e, pp*max(x)*log2e) EX2-prefolded

__device__ __forceinline__ unsigned int ford(float f) {
    unsigned int b = __float_as_uint(f);
    return (b & 0x80000000u) ? ~b : (b | 0x80000000u);
}
__device__ __forceinline__ float funord(unsigned int u) {
    unsigned int b = (u & 0x80000000u) ? (u & 0x7FFFFFFFu) : ~u;
    return __uint_as_float(b);
}
__device__ __forceinline__ float ex2(float z) {
    float r;
    asm("ex2.approx.f32 %0, %1;" : "=f"(r) : "f"(z));
    return r;
}
__device__ __forceinline__ float lg2(float z) {
    float r;
    asm("lg2.approx.f32 %0, %1;" : "=f"(r) : "f"(z));
    return r;
}

// L1: edge histograms + x-max rider (fills atomic-latency issue slots).
// EE == 3125*256 exactly, no bounds check on the edge part.
__global__ void __launch_bounds__(256) k_count_max(const int* __restrict__ ei,
                                                   const float* __restrict__ x) {
    int e = blockIdx.x * 256 + threadIdx.x;
    atomicAdd(&g_cntrow[__ldg(&ei[e])], 1);
    atomicAdd(&g_degcol[__ldg(&ei[EE + e])], 1);

    float m = -3.402823466e38f;
    const float4* x4 = (const float4*)x;
    const int n4 = (NN * DD) / 4;
    const int gsz = gridDim.x * 256;
    for (int i = e; i < n4; i += gsz) {
        float4 t = x4[i];
        m = fmaxf(m, fmaxf(fmaxf(t.x, t.y), fmaxf(t.z, t.w)));
    }
#pragma unroll
    for (int o = 16; o; o >>= 1) m = fmaxf(m, __shfl_xor_sync(~0u, m, o));
    __shared__ float sm[8];
    int lane = threadIdx.x & 31, w = threadIdx.x >> 5;
    if (lane == 0) sm[w] = m;
    __syncthreads();
    if (w == 0) {
        m = (lane < 8) ? sm[lane] : -3.402823466e38f;
#pragma unroll
        for (int o = 4; o; o >>= 1) m = fmaxf(m, __shfl_xor_sync(~0u, m, o));
        if (lane == 0) atomicMax(&g_maxbits, ford(m));
    }
}

// L2 (scan phase 1, 196 x 256): local exclusive scan of each 256-chunk of
// g_cntrow into g_off; chunk sum into g_bsum; zero g_cntrow behind itself.
__global__ void __launch_bounds__(256) k_scan1() {
    __shared__ int sh[256];
    int tid = threadIdx.x;
    int i = blockIdx.x * 256 + tid;
    int v = 0;
    if (i < NN) {
        v = g_cntrow[i];
        g_cntrow[i] = 0;          // restore zero-invariant
    }
    sh[tid] = v;
    __syncthreads();
#pragma unroll
    for (int off = 1; off < 256; off <<= 1) {
        int t = (tid >= off) ? sh[tid - off] : 0;
        __syncthreads();
        sh[tid] += t;
        __syncthreads();
    }
    if (i < NN) g_off[i] = sh[tid] - v;           // exclusive local prefix
    if (tid == 255) g_bsum[blockIdx.x] = sh[255]; // chunk total
}

// L3 (scan phase 2, 1 x 256): scan the 196 chunk sums; compute ppM.
__global__ void __launch_bounds__(256) k_scan2(const float* __restrict__ p) {
    __shared__ int sh[256];
    int tid = threadIdx.x;
    int v = (tid < NCHUNK) ? g_bsum[tid] : 0;
    sh[tid] = v;
    __syncthreads();
#pragma unroll
    for (int off = 1; off < 256; off <<= 1) {
        int t = (tid >= off) ? sh[tid - off] : 0;
        __syncthreads();
        sh[tid] += t;
        __syncthreads();
    }
    if (tid < NCHUNK) g_boff[tid] = sh[tid] - v;  // exclusive
    if (tid == 0) {
        const float LOG2E = 1.44269504088896340736f;
        float pp = 2.0f / (1.0f + __expf(-p[0]));
        float M = pp * funord(g_maxbits);
        g_ppM = make_float2(pp * LOG2E, M * LOG2E);
    }
}

// L4: scatter cols; bumps g_off[r] directly (local excl -> local incl),
// global position = local + g_boff[chunk]. Also dis/ldis + degcol zeroing.
__global__ void __launch_bounds__(256) k_scatter_dis(const int* __restrict__ ei) {
    int e = blockIdx.x * 256 + threadIdx.x;
    int r = __ldg(&ei[e]);
    int c = __ldg(&ei[EE + e]);
    int pos = atomicAdd(&g_off[r], 1) + __ldg(&g_boff[r >> 8]);
    g_scol[pos] = c;
    if (e < NN) {
        int dg = g_degcol[e];
        g_degcol[e] = 0;          // restore zero-invariant
        float M2 = g_ppM.y;
        if (dg > 0) {
            float dis = rsqrtf((float)dg);
            g_dis[e]  = dis;
            g_ldis[e] = lg2(dis) - M2;
        } else {
            g_dis[e]  = 0.0f;
            g_ldis[e] = -__int_as_float(0x7f800000); // -inf -> ex2() == 0
        }
    }
}

// L5: 64-thread block = 2 independent warps, each warp handles one node.
// Post-scatter: end = g_off[r]+boff[r>>8]; start = g_off[r-1]+boff[(r-1)>>8].
__global__ void __launch_bounds__(64) k_main(const float* __restrict__ x,
                                             const float* __restrict__ eps,
                                             float* __restrict__ out) {
    const int w    = threadIdx.x >> 5;
    const int lane = threadIdx.x & 31;
    const int r    = blockIdx.x * 2 + w;   // grid = NN/2 exactly
    const int end   = __ldg(&g_off[r]) + __ldg(&g_boff[r >> 8]);
    const int start = (r == 0) ? 0
                    : __ldg(&g_off[r - 1]) + __ldg(&g_boff[(r - 1) >> 8]);
    const float pp2 = g_ppM.x;
    const float4* __restrict__ x4 = (const float4*)x;

    __shared__ int   s_c[64];
    __shared__ float s_w[64];
    int*   sc = s_c + w * 32;
    float* sw = s_w + w * 32;

    float4 num = make_float4(0.f, 0.f, 0.f, 0.f);
    float4 den = make_float4(0.f, 0.f, 0.f, 0.f);

#define EDGE(t, lw)                                                   \
    {                                                                 \
        float ax = ex2(fmaf(pp2, (t).x, (lw)));                       \
        float ay = ex2(fmaf(pp2, (t).y, (lw)));                       \
        float az = ex2(fmaf(pp2, (t).z, (lw)));                       \
        float aw = ex2(fmaf(pp2, (t).w, (lw)));                       \
        den.x += ax; num.x = fmaf(ax, (t).x, num.x);                  \
        den.y += ay; num.y = fmaf(ay, (t).y, num.y);                  \
        den.z += az; num.z = fmaf(az, (t).z, num.z);                  \
        den.w += aw; num.w = fmaf(aw, (t).w, num.w);                  \
    }

    for (int base = start; base < end; base += 32) {
        int j = base + lane;
        if (j < end) {
            int c = g_scol[j];
            sc[lane] = c;
            sw[lane] = g_ldis[c];
        }
        __syncwarp();
        int m = end - base;
        if (m > 32) m = 32;
        int k = 0;
        for (; k + 4 <= m; k += 4) {
            int   c0 = sc[k],     c1 = sc[k + 1], c2 = sc[k + 2], c3 = sc[k + 3];
            float w0 = sw[k],     w1 = sw[k + 1], w2 = sw[k + 2], w3 = sw[k + 3];
            float4 t0 = __ldg(&x4[c0 * 32 + lane]);
            float4 t1 = __ldg(&x4[c1 * 32 + lane]);
            float4 t2 = __ldg(&x4[c2 * 32 + lane]);
            float4 t3 = __ldg(&x4[c3 * 32 + lane]);
            EDGE(t0, w0) EDGE(t1, w1) EDGE(t2, w2) EDGE(t3, w3)
        }
        for (; k < m; k++) {
            int   c = sc[k];
            float lw = sw[k];
            float4 t = __ldg(&x4[c * 32 + lane]);
            EDGE(t, lw)
        }
        __syncwarp();
    }
#undef EDGE

    float dr = g_dis[r];
    float e1 = 1.0f + eps[0];
    float4 xv = __ldg(&x4[r * 32 + lane]);
    float4 o;
    o.x = __fdividef(dr * num.x, fmaf(dr, den.x, 1e-6f)) + e1 * xv.x;
    o.y = __fdividef(dr * num.y, fmaf(dr, den.y, 1e-6f)) + e1 * xv.y;
    o.z = __fdividef(dr * num.z, fmaf(dr, den.z, 1e-6f)) + e1 * xv.z;
    o.w = __fdividef(dr * num.w, fmaf(dr, den.w, 1e-6f)) + e1 * xv.w;
    ((float4*)out)[r * 32 + lane] = o;
}

extern "C" void kernel_launch(void* const* d_in, const int* in_sizes, int n_in,
                              void* d_out, int out_size) {
    const float* x   = (const float*)d_in[0];
    const int*   ei  = (const int*)d_in[1];
    const float* eps = (const float*)d_in[2];
    const float* p   = (const float*)d_in[3];
    float* out = (float*)d_out;

    k_count_max  <<<EE / 256, 256>>>(ei, x);
    k_scan1      <<<NCHUNK, 256>>>();
    k_scan2      <<<1, 256>>>(p);
    k_scatter_dis<<<EE / 256, 256>>>(ei);
    k_main       <<<NN / 2, 64>>>(x, eps, out);
}